// round 4
// baseline (speedup 1.0000x reference)
#include <cuda_runtime.h>
#include <cuda_bf16.h>

// Segmented layer norm: per-segment, per-feature mean/var over ragged rows.
// inputs (metadata order): [0] input f32 [N,64], [1] offsets i32 [S] (cumulative ends),
//                          [2] weight f32 [64], [3] bias f32 [64]
// output: f32 [N,64]
//
// One CTA per segment (S=8192). 256 threads: thread t -> float4 chunk (t&15)
// of row-group (t>>4). Pass 1 accumulates per-feature sum/sumsq in registers
// (2x unrolled for MLP=2), reduces via smem, folds to a[f]=w*rstd,
// b[f]=bias-mean*a. Pass 2: out = x*a + b (re-read hits L2; segment ~64KB).

#define TPB 256
#define EPS 1e-5f

__global__ __launch_bounds__(TPB) void seg_ln_kernel(
    const float* __restrict__ x,
    const int*   __restrict__ offsets,
    const float* __restrict__ weight,
    const float* __restrict__ bias,
    float*       __restrict__ out)
{
    const int s = blockIdx.x;
    const int t = threadIdx.x;

    const int start = (s == 0) ? 0 : offsets[s - 1];
    const int end   = offsets[s];

    __shared__ float sm_sum[TPB][4];
    __shared__ float sm_sq [TPB][4];
    __shared__ float sm_a[64];
    __shared__ float sm_b[64];

    const int chunk = t & 15;   // which float4 within the 64-float row
    const int rgrp  = t >> 4;   // row offset within a 16-row group

    const float4* __restrict__ xv = reinterpret_cast<const float4*>(x);
    float4*       __restrict__ ov = reinterpret_cast<float4*>(out);

    // ---- Pass 1: per-feature sum and sum of squares (2x unrolled, MLP=2) ----
    float4 acc  = make_float4(0.f, 0.f, 0.f, 0.f);
    float4 accq = make_float4(0.f, 0.f, 0.f, 0.f);

    int r = start + rgrp;
    for (; r + 16 < end; r += 32) {
        float4 v0 = __ldg(&xv[(size_t)r * 16 + chunk]);
        float4 v1 = __ldg(&xv[(size_t)(r + 16) * 16 + chunk]);
        acc.x += v0.x; acc.y += v0.y; acc.z += v0.z; acc.w += v0.w;
        accq.x = fmaf(v0.x, v0.x, accq.x); accq.y = fmaf(v0.y, v0.y, accq.y);
        accq.z = fmaf(v0.z, v0.z, accq.z); accq.w = fmaf(v0.w, v0.w, accq.w);
        acc.x += v1.x; acc.y += v1.y; acc.z += v1.z; acc.w += v1.w;
        accq.x = fmaf(v1.x, v1.x, accq.x); accq.y = fmaf(v1.y, v1.y, accq.y);
        accq.z = fmaf(v1.z, v1.z, accq.z); accq.w = fmaf(v1.w, v1.w, accq.w);
    }
    if (r < end) {
        float4 v = __ldg(&xv[(size_t)r * 16 + chunk]);
        acc.x += v.x; acc.y += v.y; acc.z += v.z; acc.w += v.w;
        accq.x = fmaf(v.x, v.x, accq.x); accq.y = fmaf(v.y, v.y, accq.y);
        accq.z = fmaf(v.z, v.z, accq.z); accq.w = fmaf(v.w, v.w, accq.w);
    }

    sm_sum[t][0] = acc.x;  sm_sum[t][1] = acc.y;  sm_sum[t][2] = acc.z;  sm_sum[t][3] = acc.w;
    sm_sq [t][0] = accq.x; sm_sq [t][1] = accq.y; sm_sq [t][2] = accq.z; sm_sq [t][3] = accq.w;
    __syncthreads();

    // ---- Reduce 16 partials per feature; fold scale/shift ----
    if (t < 64) {
        const int c = t >> 2;   // chunk index for this feature
        const int k = t & 3;    // component within chunk
        float fsum = 0.f, fsq = 0.f;
        #pragma unroll
        for (int g = 0; g < 16; ++g) {
            fsum += sm_sum[c + 16 * g][k];
            fsq  += sm_sq [c + 16 * g][k];
        }
        const float inv  = 1.0f / (float)(end - start);
        const float mean = fsum * inv;
        float var = fsq * inv - mean * mean;
        var = fmaxf(var, 0.0f);
        const float rstd = rsqrtf(var + EPS);
        const float a = weight[t] * rstd;
        sm_a[t] = a;
        sm_b[t] = bias[t] - mean * a;
    }
    __syncthreads();

    const float4 av = reinterpret_cast<const float4*>(sm_a)[chunk];
    const float4 bv = reinterpret_cast<const float4*>(sm_b)[chunk];

    // ---- Pass 2: normalize + affine (reads hit L2; 2x unrolled) ----
    r = start + rgrp;
    for (; r + 16 < end; r += 32) {
        const size_t i0 = (size_t)r * 16 + chunk;
        const size_t i1 = (size_t)(r + 16) * 16 + chunk;
        float4 v0 = xv[i0];
        float4 v1 = xv[i1];
        float4 w0, w1;
        w0.x = fmaf(v0.x, av.x, bv.x); w0.y = fmaf(v0.y, av.y, bv.y);
        w0.z = fmaf(v0.z, av.z, bv.z); w0.w = fmaf(v0.w, av.w, bv.w);
        w1.x = fmaf(v1.x, av.x, bv.x); w1.y = fmaf(v1.y, av.y, bv.y);
        w1.z = fmaf(v1.z, av.z, bv.z); w1.w = fmaf(v1.w, av.w, bv.w);
        ov[i0] = w0;
        ov[i1] = w1;
    }
    if (r < end) {
        const size_t idx = (size_t)r * 16 + chunk;
        float4 v = xv[idx];
        float4 w;
        w.x = fmaf(v.x, av.x, bv.x); w.y = fmaf(v.y, av.y, bv.y);
        w.z = fmaf(v.z, av.z, bv.z); w.w = fmaf(v.w, av.w, bv.w);
        ov[idx] = w;
    }
}

extern "C" void kernel_launch(void* const* d_in, const int* in_sizes, int n_in,
                              void* d_out, int out_size)
{
    const float* x       = (const float*)d_in[0];
    const int*   offsets = (const int*)  d_in[1];
    const float* weight  = (const float*)d_in[2];
    const float* bias    = (const float*)d_in[3];
    float*       out     = (float*)d_out;

    const int S = in_sizes[1];
    seg_ln_kernel<<<S, TPB>>>(x, offsets, weight, bias, out);
}

// round 5
// speedup vs baseline: 1.0107x; 1.0107x over previous
#include <cuda_runtime.h>
#include <cuda_bf16.h>

// Segmented layer norm, smem-cached single-read version.
// inputs: [0] input f32 [N,64], [1] offsets i32 [S] (cumulative ends),
//         [2] weight f32 [64], [3] bias f32 [64] ; output f32 [N,64]
//
// One CTA per segment. Pass 1 streams the segment from HBM ONCE, caching rows
// in dynamic smem (432-row cap = 108KB; segments are ~256±16 rows so overflow
// is ~impossible, but a global fallback keeps correctness). Pass 2 normalizes
// from smem. DRAM traffic = exactly 512MB read + 512MB write.
// 2 CTAs/SM (smem-limited); warp-shuffle pre-reduction keeps static smem small.

#define TPB 256
#define CAP_ROWS 432          // 432 rows * 256 B = 110592 B dynamic smem
#define EPS 1e-5f

extern __shared__ float4 s_cache[];   // [CAP_ROWS * 16]

__global__ __launch_bounds__(TPB, 2) void seg_ln_kernel(
    const float* __restrict__ x,
    const int*   __restrict__ offsets,
    const float* __restrict__ weight,
    const float* __restrict__ bias,
    float*       __restrict__ out)
{
    const int s = blockIdx.x;
    const int t = threadIdx.x;

    const int start = (s == 0) ? 0 : offsets[s - 1];
    const int end   = offsets[s];

    __shared__ float sm_sum[128][4];  // 8 warps x 16 chunks
    __shared__ float sm_sq [128][4];
    __shared__ float sm_a[64];
    __shared__ float sm_b[64];

    const int chunk = t & 15;   // float4 chunk within the 64-float row
    const int rgrp  = t >> 4;   // row offset within a 16-row group
    const int lane  = t & 31;
    const int warp  = t >> 5;

    const float4* __restrict__ xv = reinterpret_cast<const float4*>(x);
    float4*       __restrict__ ov = reinterpret_cast<float4*>(out);

    // ---- Pass 1: stream from HBM, cache in smem, accumulate sum/sumsq ----
    float4 acc  = make_float4(0.f, 0.f, 0.f, 0.f);
    float4 accq = make_float4(0.f, 0.f, 0.f, 0.f);

    int r  = start + rgrp;
    int cr = rgrp;

    // 4x unrolled main loop (MLP=4)
    for (; r + 48 < end; r += 64, cr += 64) {
        float4 v0 = __ldg(&xv[(size_t)(r     ) * 16 + chunk]);
        float4 v1 = __ldg(&xv[(size_t)(r + 16) * 16 + chunk]);
        float4 v2 = __ldg(&xv[(size_t)(r + 32) * 16 + chunk]);
        float4 v3 = __ldg(&xv[(size_t)(r + 48) * 16 + chunk]);
        if (cr      < CAP_ROWS) s_cache[(cr     ) * 16 + chunk] = v0;
        if (cr + 16 < CAP_ROWS) s_cache[(cr + 16) * 16 + chunk] = v1;
        if (cr + 32 < CAP_ROWS) s_cache[(cr + 32) * 16 + chunk] = v2;
        if (cr + 48 < CAP_ROWS) s_cache[(cr + 48) * 16 + chunk] = v3;
        acc.x += v0.x + v1.x + v2.x + v3.x;
        acc.y += v0.y + v1.y + v2.y + v3.y;
        acc.z += v0.z + v1.z + v2.z + v3.z;
        acc.w += v0.w + v1.w + v2.w + v3.w;
        accq.x = fmaf(v0.x, v0.x, fmaf(v1.x, v1.x, fmaf(v2.x, v2.x, fmaf(v3.x, v3.x, accq.x))));
        accq.y = fmaf(v0.y, v0.y, fmaf(v1.y, v1.y, fmaf(v2.y, v2.y, fmaf(v3.y, v3.y, accq.y))));
        accq.z = fmaf(v0.z, v0.z, fmaf(v1.z, v1.z, fmaf(v2.z, v2.z, fmaf(v3.z, v3.z, accq.z))));
        accq.w = fmaf(v0.w, v0.w, fmaf(v1.w, v1.w, fmaf(v2.w, v2.w, fmaf(v3.w, v3.w, accq.w))));
    }
    for (; r < end; r += 16, cr += 16) {
        float4 v = __ldg(&xv[(size_t)r * 16 + chunk]);
        if (cr < CAP_ROWS) s_cache[cr * 16 + chunk] = v;
        acc.x += v.x; acc.y += v.y; acc.z += v.z; acc.w += v.w;
        accq.x = fmaf(v.x, v.x, accq.x); accq.y = fmaf(v.y, v.y, accq.y);
        accq.z = fmaf(v.z, v.z, accq.z); accq.w = fmaf(v.w, v.w, accq.w);
    }

    // ---- Warp-level pre-reduction: fold rgrp pairs (lanes L and L^16) ----
    acc.x  += __shfl_xor_sync(0xffffffffu, acc.x,  16);
    acc.y  += __shfl_xor_sync(0xffffffffu, acc.y,  16);
    acc.z  += __shfl_xor_sync(0xffffffffu, acc.z,  16);
    acc.w  += __shfl_xor_sync(0xffffffffu, acc.w,  16);
    accq.x += __shfl_xor_sync(0xffffffffu, accq.x, 16);
    accq.y += __shfl_xor_sync(0xffffffffu, accq.y, 16);
    accq.z += __shfl_xor_sync(0xffffffffu, accq.z, 16);
    accq.w += __shfl_xor_sync(0xffffffffu, accq.w, 16);
    if (lane < 16) {
        sm_sum[warp * 16 + chunk][0] = acc.x;
        sm_sum[warp * 16 + chunk][1] = acc.y;
        sm_sum[warp * 16 + chunk][2] = acc.z;
        sm_sum[warp * 16 + chunk][3] = acc.w;
        sm_sq [warp * 16 + chunk][0] = accq.x;
        sm_sq [warp * 16 + chunk][1] = accq.y;
        sm_sq [warp * 16 + chunk][2] = accq.z;
        sm_sq [warp * 16 + chunk][3] = accq.w;
    }
    __syncthreads();

    // ---- Final reduction over 8 warp-partials; fold scale/shift ----
    if (t < 64) {
        const int c = t >> 2;
        const int k = t & 3;
        float fsum = 0.f, fsq = 0.f;
        #pragma unroll
        for (int w = 0; w < 8; ++w) {
            fsum += sm_sum[w * 16 + c][k];
            fsq  += sm_sq [w * 16 + c][k];
        }
        const float inv  = 1.0f / (float)(end - start);
        const float mean = fsum * inv;
        float var = fsq * inv - mean * mean;
        var = fmaxf(var, 0.0f);
        const float rstd = rsqrtf(var + EPS);
        const float a = weight[t] * rstd;
        sm_a[t] = a;
        sm_b[t] = bias[t] - mean * a;
    }
    __syncthreads();

    const float4 av = reinterpret_cast<const float4*>(sm_a)[chunk];
    const float4 bv = reinterpret_cast<const float4*>(sm_b)[chunk];

    // ---- Pass 2: normalize from smem cache (global fallback for overflow) ----
    r = start + rgrp; cr = rgrp;
    for (; r + 16 < end; r += 32, cr += 32) {
        float4 v0 = (cr      < CAP_ROWS) ? s_cache[(cr     ) * 16 + chunk]
                                         : xv[(size_t)(r     ) * 16 + chunk];
        float4 v1 = (cr + 16 < CAP_ROWS) ? s_cache[(cr + 16) * 16 + chunk]
                                         : xv[(size_t)(r + 16) * 16 + chunk];
        float4 w0, w1;
        w0.x = fmaf(v0.x, av.x, bv.x); w0.y = fmaf(v0.y, av.y, bv.y);
        w0.z = fmaf(v0.z, av.z, bv.z); w0.w = fmaf(v0.w, av.w, bv.w);
        w1.x = fmaf(v1.x, av.x, bv.x); w1.y = fmaf(v1.y, av.y, bv.y);
        w1.z = fmaf(v1.z, av.z, bv.z); w1.w = fmaf(v1.w, av.w, bv.w);
        ov[(size_t)(r     ) * 16 + chunk] = w0;
        ov[(size_t)(r + 16) * 16 + chunk] = w1;
    }
    if (r < end) {
        float4 v = (cr < CAP_ROWS) ? s_cache[cr * 16 + chunk]
                                   : xv[(size_t)r * 16 + chunk];
        float4 w;
        w.x = fmaf(v.x, av.x, bv.x); w.y = fmaf(v.y, av.y, bv.y);
        w.z = fmaf(v.z, av.z, bv.z); w.w = fmaf(v.w, av.w, bv.w);
        ov[(size_t)r * 16 + chunk] = w;
    }
}

extern "C" void kernel_launch(void* const* d_in, const int* in_sizes, int n_in,
                              void* d_out, int out_size)
{
    const float* x       = (const float*)d_in[0];
    const int*   offsets = (const int*)  d_in[1];
    const float* weight  = (const float*)d_in[2];
    const float* bias    = (const float*)d_in[3];
    float*       out     = (float*)d_out;

    const int S = in_sizes[1];
    const int dyn_smem = CAP_ROWS * 16 * sizeof(float4);  // 110592 B

    // Immediate (non-stream) call: legal during graph capture, idempotent.
    cudaFuncSetAttribute(seg_ln_kernel,
                         cudaFuncAttributeMaxDynamicSharedMemorySize, dyn_smem);

    seg_ln_kernel<<<S, TPB, dyn_smem>>>(x, offsets, weight, bias, out);
}

// round 7
// speedup vs baseline: 1.3697x; 1.3552x over previous
#include <cuda_runtime.h>
#include <cuda_bf16.h>
#include <cstdint>

// Segmented layer norm, TMA-bulk-cached single-read version.
// inputs: [0] input f32 [N,64], [1] offsets i32 [S] (cumulative ends),
//         [2] weight f32 [64], [3] bias f32 [64] ; output f32 [N,64]
//
// One CTA per segment (S=8192). One cp.async.bulk per CTA streams the whole
// segment (<=400 rows = 100KB) HBM->smem via mbarrier (TMA engine supplies the
// MLP; warps never wait on individual LDGs). Pass 1 computes per-feature
// sum/sumsq from smem, reduces via shuffle+smem, folds a=w*rstd, b=bias-mean*a.
// Pass 2 normalizes from smem and stores. DRAM traffic = 512MB read + 512MB
// write exactly. TPB=512, 2 CTAs/SM (32 warps) for issue/latency hiding.

#define TPB 512
#define CAP_ROWS 400              // 400 rows * 256B = 102400 B dynamic smem
#define EPS 1e-5f

extern __shared__ float4 s_cache[];   // [CAP_ROWS * 16]

__device__ __forceinline__ uint32_t smem_u32(const void* p) {
    uint32_t a;
    asm("{ .reg .u64 t; cvta.to.shared.u64 t, %1; cvt.u32.u64 %0, t; }"
        : "=r"(a) : "l"(p));
    return a;
}

__global__ __launch_bounds__(TPB, 2) void seg_ln_kernel(
    const float* __restrict__ x,
    const int*   __restrict__ offsets,
    const float* __restrict__ weight,
    const float* __restrict__ bias,
    float*       __restrict__ out)
{
    const int s = blockIdx.x;
    const int t = threadIdx.x;

    const int start = (s == 0) ? 0 : offsets[s - 1];
    const int end   = offsets[s];
    const int len   = end - start;
    const int crows = (len < CAP_ROWS) ? len : CAP_ROWS;   // rows in smem cache

    __shared__ float sm_sum[16][16][4];   // [warp][chunk][component]
    __shared__ float sm_sq [16][16][4];
    __shared__ float sm_a[64];
    __shared__ float sm_b[64];
    __shared__ uint64_t sm_mbar;

    const int chunk = t & 15;     // float4 chunk within the 64-float row
    const int rgrp  = t >> 4;     // row offset within a 32-row group (0..31)
    const int lane  = t & 31;
    const int warp  = t >> 5;

    const float4* __restrict__ xv = reinterpret_cast<const float4*>(x);
    float4*       __restrict__ ov = reinterpret_cast<float4*>(out);

    const uint32_t mbar = smem_u32(&sm_mbar);
    const uint32_t cache_base = smem_u32(s_cache);
    const uint32_t bytes = (uint32_t)crows * 256u;

    // ---- Issue one bulk async copy for the whole cached segment ----
    if (t == 0) {
        asm volatile("mbarrier.init.shared.b64 [%0], %1;"
                     :: "r"(mbar), "r"(1) : "memory");
    }
    __syncthreads();
    if (t == 0) {
        asm volatile("mbarrier.arrive.expect_tx.shared.b64 _, [%0], %1;"
                     :: "r"(mbar), "r"(bytes) : "memory");
        asm volatile(
            "cp.async.bulk.shared::cluster.global.mbarrier::complete_tx::bytes "
            "[%0], [%1], %2, [%3];"
            :: "r"(cache_base), "l"(xv + (size_t)start * 16), "r"(bytes),
               "r"(mbar) : "memory");
    }

    // ---- Wait for the copy (acquire so following LDS are ordered) ----
    {
        uint32_t done = 0;
        while (!done) {
            asm volatile(
                "{ .reg .pred p;\n"
                "  mbarrier.try_wait.parity.acquire.cta.shared::cta.b64 p, [%1], %2, 0x989680;\n"
                "  selp.b32 %0, 1, 0, p; }"
                : "=r"(done) : "r"(mbar), "r"(0u) : "memory");
        }
    }

    // ---- Pass 1: per-feature sum / sumsq from smem (rare tail from global) ----
    float4 acc  = make_float4(0.f, 0.f, 0.f, 0.f);
    float4 accq = make_float4(0.f, 0.f, 0.f, 0.f);

    int r = rgrp;
    for (; r + 32 < crows; r += 64) {
        float4 v0 = s_cache[(r     ) * 16 + chunk];
        float4 v1 = s_cache[(r + 32) * 16 + chunk];
        acc.x += v0.x + v1.x; acc.y += v0.y + v1.y;
        acc.z += v0.z + v1.z; acc.w += v0.w + v1.w;
        accq.x = fmaf(v0.x, v0.x, fmaf(v1.x, v1.x, accq.x));
        accq.y = fmaf(v0.y, v0.y, fmaf(v1.y, v1.y, accq.y));
        accq.z = fmaf(v0.z, v0.z, fmaf(v1.z, v1.z, accq.z));
        accq.w = fmaf(v0.w, v0.w, fmaf(v1.w, v1.w, accq.w));
    }
    if (r < crows) {
        float4 v = s_cache[r * 16 + chunk];
        acc.x += v.x; acc.y += v.y; acc.z += v.z; acc.w += v.w;
        accq.x = fmaf(v.x, v.x, accq.x); accq.y = fmaf(v.y, v.y, accq.y);
        accq.z = fmaf(v.z, v.z, accq.z); accq.w = fmaf(v.w, v.w, accq.w);
    }
    // Overflow tail (essentially never taken; correctness guard)
    for (int rr = CAP_ROWS + rgrp; rr < len; rr += 32) {
        float4 v = __ldg(&xv[(size_t)(start + rr) * 16 + chunk]);
        acc.x += v.x; acc.y += v.y; acc.z += v.z; acc.w += v.w;
        accq.x = fmaf(v.x, v.x, accq.x); accq.y = fmaf(v.y, v.y, accq.y);
        accq.z = fmaf(v.z, v.z, accq.z); accq.w = fmaf(v.w, v.w, accq.w);
    }

    // ---- Warp fold: lanes L and L^16 share a chunk, differ in rgrp ----
    acc.x  += __shfl_xor_sync(0xffffffffu, acc.x,  16);
    acc.y  += __shfl_xor_sync(0xffffffffu, acc.y,  16);
    acc.z  += __shfl_xor_sync(0xffffffffu, acc.z,  16);
    acc.w  += __shfl_xor_sync(0xffffffffu, acc.w,  16);
    accq.x += __shfl_xor_sync(0xffffffffu, accq.x, 16);
    accq.y += __shfl_xor_sync(0xffffffffu, accq.y, 16);
    accq.z += __shfl_xor_sync(0xffffffffu, accq.z, 16);
    accq.w += __shfl_xor_sync(0xffffffffu, accq.w, 16);
    if (lane < 16) {
        sm_sum[warp][chunk][0] = acc.x;  sm_sum[warp][chunk][1] = acc.y;
        sm_sum[warp][chunk][2] = acc.z;  sm_sum[warp][chunk][3] = acc.w;
        sm_sq [warp][chunk][0] = accq.x; sm_sq [warp][chunk][1] = accq.y;
        sm_sq [warp][chunk][2] = accq.z; sm_sq [warp][chunk][3] = accq.w;
    }
    __syncthreads();

    // ---- Final reduce over 16 warps; fold scale/shift per feature ----
    if (t < 64) {
        const int c = t >> 2;
        const int k = t & 3;
        float fsum = 0.f, fsq = 0.f;
        #pragma unroll
        for (int w = 0; w < 16; ++w) {
            fsum += sm_sum[w][c][k];
            fsq  += sm_sq [w][c][k];
        }
        const float inv  = 1.0f / (float)len;
        const float mean = fsum * inv;
        float var = fsq * inv - mean * mean;
        var = fmaxf(var, 0.0f);
        const float rstd = rsqrtf(var + EPS);
        const float a = weight[t] * rstd;
        sm_a[t] = a;
        sm_b[t] = bias[t] - mean * a;
    }
    __syncthreads();

    const float4 av = reinterpret_cast<const float4*>(sm_a)[chunk];
    const float4 bv = reinterpret_cast<const float4*>(sm_b)[chunk];

    // ---- Pass 2: normalize from smem, store ----
    r = rgrp;
    for (; r + 32 < crows; r += 64) {
        float4 v0 = s_cache[(r     ) * 16 + chunk];
        float4 v1 = s_cache[(r + 32) * 16 + chunk];
        float4 w0, w1;
        w0.x = fmaf(v0.x, av.x, bv.x); w0.y = fmaf(v0.y, av.y, bv.y);
        w0.z = fmaf(v0.z, av.z, bv.z); w0.w = fmaf(v0.w, av.w, bv.w);
        w1.x = fmaf(v1.x, av.x, bv.x); w1.y = fmaf(v1.y, av.y, bv.y);
        w1.z = fmaf(v1.z, av.z, bv.z); w1.w = fmaf(v1.w, av.w, bv.w);
        ov[(size_t)(start + r     ) * 16 + chunk] = w0;
        ov[(size_t)(start + r + 32) * 16 + chunk] = w1;
    }
    if (r < crows) {
        float4 v = s_cache[r * 16 + chunk];
        float4 w;
        w.x = fmaf(v.x, av.x, bv.x); w.y = fmaf(v.y, av.y, bv.y);
        w.z = fmaf(v.z, av.z, bv.z); w.w = fmaf(v.w, av.w, bv.w);
        ov[(size_t)(start + r) * 16 + chunk] = w;
    }
    // Overflow tail (essentially never taken)
    for (int rr = CAP_ROWS + rgrp; rr < len; rr += 32) {
        float4 v = __ldg(&xv[(size_t)(start + rr) * 16 + chunk]);
        float4 w;
        w.x = fmaf(v.x, av.x, bv.x); w.y = fmaf(v.y, av.y, bv.y);
        w.z = fmaf(v.z, av.z, bv.z); w.w = fmaf(v.w, av.w, bv.w);
        ov[(size_t)(start + rr) * 16 + chunk] = w;
    }
}

extern "C" void kernel_launch(void* const* d_in, const int* in_sizes, int n_in,
                              void* d_out, int out_size)
{
    const float* x       = (const float*)d_in[0];
    const int*   offsets = (const int*)  d_in[1];
    const float* weight  = (const float*)d_in[2];
    const float* bias    = (const float*)d_in[3];
    float*       out     = (float*)d_out;

    const int S = in_sizes[1];
    const int dyn_smem = CAP_ROWS * 16 * sizeof(float4);  // 102400 B

    cudaFuncSetAttribute(seg_ln_kernel,
                         cudaFuncAttributeMaxDynamicSharedMemorySize, dyn_smem);

    seg_ln_kernel<<<S, TPB, dyn_smem>>>(x, offsets, weight, bias, out);
}